// round 4
// baseline (speedup 1.0000x reference)
#include <cuda_runtime.h>
#include <cuda_bf16.h>

#define NTH 128
#define SEQ 101
#define HPAD 20   // padded row stride for D=16 activations (bank-conflict-free)

// q pre-scale: (1/sqrt(head_dim=2)) * log2(e), so exp(score) == exp2(q'.k)
#define QSC (0.7071067811865476f * 1.4426950408889634f)

typedef unsigned long long ull;

__device__ __forceinline__ ull pack2(float a, float b) {
    ull r; asm("mov.b64 %0, {%1, %2};" : "=l"(r) : "f"(a), "f"(b)); return r;
}
__device__ __forceinline__ void unpack2(ull p, float& a, float& b) {
    asm("mov.b64 {%0, %1}, %2;" : "=f"(a), "=f"(b) : "l"(p));
}
__device__ __forceinline__ ull fma2u(ull a, ull b, ull c) {
    ull d; asm("fma.rn.f32x2 %0, %1, %2, %3;" : "=l"(d) : "l"(a), "l"(b), "l"(c)); return d;
}
__device__ __forceinline__ ull mul2u(ull a, ull b) {
    ull d; asm("mul.rn.f32x2 %0, %1, %2;" : "=l"(d) : "l"(a), "l"(b)); return d;
}
__device__ __forceinline__ ull add2u(ull a, ull b) {
    ull d; asm("add.rn.f32x2 %0, %1, %2;" : "=l"(d) : "l"(a), "l"(b)); return d;
}
__device__ __forceinline__ float ex2f(float x) {
    float e; asm("ex2.approx.ftz.f32 %0, %1;" : "=f"(e) : "f"(x)); return e;
}

__global__ __launch_bounds__(NTH, 4) void TorrinE0_kernel(
    const float* __restrict__ x,
    const float* __restrict__ conv_w,
    const float* __restrict__ conv_b,
    const float* __restrict__ cls_emb,
    const float* __restrict__ Wqkv,
    const float* __restrict__ bqkv,
    const float* __restrict__ Wo,
    const float* __restrict__ bo,
    const float* __restrict__ W1,
    const float* __restrict__ b1,
    const float* __restrict__ W2,
    const float* __restrict__ b2,
    const float* __restrict__ ln1g, const float* __restrict__ ln1b,
    const float* __restrict__ ln2g, const float* __restrict__ ln2b,
    const float* __restrict__ lnfg, const float* __restrict__ lnfb,
    const float* __restrict__ endw, const float* __restrict__ endb,
    const float* __restrict__ headw, const float* __restrict__ headb,
    float* __restrict__ out)
{
    __shared__ float  s_h[SEQ * HPAD];    // hidden state, padded rows
    __shared__ float2 s_q[8 * SEQ];       // [h][s]  pre-scaled q
    __shared__ float4 s_kv[8 * SEQ];      // [h][t]  {k0,k1,v0,v1}
    __shared__ float  s_buf[3500];        // x staging; later ctx[SEQ*HPAD] + head scratch
    __shared__ float  s_wq[768];          // Wqkv for current layer (prefetched)
    __shared__ float  s_wo[256], s_w1[256], s_w2[256];
    __shared__ float  s_cw[560];
    __shared__ float  s_bq[48];
    __shared__ float  s_bo[16], s_b1[16], s_b2[16];
    __shared__ float  s_g1[16], s_be1[16], s_g2[16], s_be2[16], s_cb[16];

    const int tid = threadIdx.x;
    const int b   = blockIdx.x;

    // ---- stage x row + conv weights + layer-0 Wqkv ----
    {
        const float4* xg = (const float4*)(x + (size_t)b * 3500);
        float4* xb = (float4*)s_buf;
        #pragma unroll 2
        for (int i = tid; i < 875; i += NTH) xb[i] = xg[i];
        for (int i = tid; i < 560; i += NTH) s_cw[i] = conv_w[i];
        for (int i = tid; i < 768; i += NTH) s_wq[i] = Wqkv[i];   // layer 0
        if (tid < 48) s_bq[tid] = bqkv[tid];
        if (tid < 16) {
            s_h[tid]  = cls_emb[tid];    // cls token = row 0
            s_cb[tid] = conv_b[tid];
        }
    }
    __syncthreads();

    // ---- conv patchifier: 100 patches x 16 filters, K=35 ----
    for (int idx = tid; idx < 1600; idx += NTH) {
        const int p = idx >> 4, f = idx & 15;
        const float* xp = s_buf + p * 35;
        const float* wf = s_cw + f * 35;
        float acc = s_cb[f];
        #pragma unroll
        for (int k = 0; k < 35; k++) acc = fmaf(xp[k], wf[k], acc);
        s_h[(p + 1) * HPAD + f] = acc;
    }
    __syncthreads();

    for (int l = 0; l < 8; l++) {
        // ---- stage non-QKV weights for this layer (Wqkv already resident) ----
        for (int i = tid; i < 256; i += NTH) {
            s_wo[i] = Wo[l * 256 + i];
            s_w1[i] = W1[l * 256 + i];
            s_w2[i] = W2[l * 256 + i];
        }
        if (tid < 16) {
            s_bo[tid]  = bo[l * 16 + tid];
            s_b1[tid]  = b1[l * 16 + tid];
            s_b2[tid]  = b2[l * 16 + tid];
            s_g1[tid]  = ln1g[l * 16 + tid];
            s_be1[tid] = ln1b[l * 16 + tid];
            s_g2[tid]  = ln2g[l * 16 + tid];
            s_be2[tid] = ln2b[l * 16 + tid];
        }
        __syncthreads();

        // ---- QKV projection: one thread per token; weight reads broadcast ----
        for (int s = tid; s < SEQ; s += NTH) {
            float hr[16];
            const float4* h4 = (const float4*)(s_h + s * HPAD);
            #pragma unroll
            for (int j = 0; j < 4; j++) {
                const float4 v = h4[j];
                hr[4*j] = v.x; hr[4*j+1] = v.y; hr[4*j+2] = v.z; hr[4*j+3] = v.w;
            }
            #pragma unroll
            for (int h = 0; h < 8; h++) {
                float acc[6];
                #pragma unroll
                for (int r = 0; r < 6; r++) {
                    const int e = (r >> 1) * 16 + 2 * h + (r & 1);
                    const float4* w4 = (const float4*)(s_wq + e * 16);
                    float a = s_bq[e];
                    #pragma unroll
                    for (int j = 0; j < 4; j++) {
                        const float4 wv = w4[j];
                        a = fmaf(hr[4*j],   wv.x, a);
                        a = fmaf(hr[4*j+1], wv.y, a);
                        a = fmaf(hr[4*j+2], wv.z, a);
                        a = fmaf(hr[4*j+3], wv.w, a);
                    }
                    acc[r] = a;
                }
                s_q[h * SEQ + s]  = make_float2(acc[0] * QSC, acc[1] * QSC);
                s_kv[h * SEQ + s] = make_float4(acc[2], acc[3], acc[4], acc[5]);
            }
        }
        __syncthreads();

        // ---- attention: warps 0-1 (64 threads) = 8 threads/head x 13 queries.
        //      Dense warps: only 104 slots issued per head for 101 queries.
        //      Warps 2-3 prefetch next layer's Wqkv (s_wq dead after QKV). ----
        if (tid < 64) {
            const int h  = tid >> 3;          // 0..7
            const int j  = tid & 7;           // 0..7
            const int s0 = j * 13;            // 13 queries per thread
            const float2* qh = s_q + h * SEQ;

            ull q0p[6], q1p[6];
            #pragma unroll
            for (int p = 0; p < 6; p++) {
                const float2 qa = qh[min(s0 + 2*p,     SEQ - 1)];
                const float2 qb = qh[min(s0 + 2*p + 1, SEQ - 1)];
                q0p[p] = pack2(qa.x, qb.x);
                q1p[p] = pack2(qa.y, qb.y);
            }
            const float2 qs = qh[min(s0 + 12, SEQ - 1)];

            ull sum2[6], c0p[6], c1p[6];
            #pragma unroll
            for (int p = 0; p < 6; p++) {
                sum2[p] = pack2(0.f, 0.f);
                c0p[p]  = pack2(0.f, 0.f);
                c1p[p]  = pack2(0.f, 0.f);
            }
            float sums = 0.f, c0s = 0.f, c1s = 0.f;

            const float4* kp = s_kv + h * SEQ;
            #pragma unroll 2
            for (int t = 0; t < SEQ; t++) {
                const float4 kv = kp[t];
                const ull k0b = pack2(kv.x, kv.x);
                const ull k1b = pack2(kv.y, kv.y);
                const ull v0b = pack2(kv.z, kv.z);
                const ull v1b = pack2(kv.w, kv.w);
                #pragma unroll
                for (int p = 0; p < 6; p++) {
                    const ull sc2 = fma2u(q1p[p], k1b, mul2u(q0p[p], k0b));
                    float sa, sb;
                    unpack2(sc2, sa, sb);
                    const ull e01 = pack2(ex2f(sa), ex2f(sb));
                    sum2[p] = add2u(sum2[p], e01);
                    c0p[p]  = fma2u(e01, v0b, c0p[p]);
                    c1p[p]  = fma2u(e01, v1b, c1p[p]);
                }
                const float sc = fmaf(qs.x, kv.x, qs.y * kv.y);
                const float e  = ex2f(sc);
                sums += e;
                c0s = fmaf(e, kv.z, c0s);
                c1s = fmaf(e, kv.w, c1s);
            }
            #pragma unroll
            for (int p = 0; p < 6; p++) {
                float sa, sb, a0, b0, a1, b1;
                unpack2(sum2[p], sa, sb);
                unpack2(c0p[p],  a0, b0);
                unpack2(c1p[p],  a1, b1);
                const int s_a = min(s0 + 2*p,     SEQ - 1);
                const int s_b = min(s0 + 2*p + 1, SEQ - 1);
                const float ia = __fdividef(1.f, sa);
                const float ib = __fdividef(1.f, sb);
                *(float2*)(s_buf + s_a * HPAD + 2*h) = make_float2(a0 * ia, a1 * ia);
                *(float2*)(s_buf + s_b * HPAD + 2*h) = make_float2(b0 * ib, b1 * ib);
            }
            {
                const int s = min(s0 + 12, SEQ - 1);
                const float inv = __fdividef(1.f, sums);
                *(float2*)(s_buf + s * HPAD + 2*h) = make_float2(c0s * inv, c1s * inv);
            }
        } else if (l < 7) {
            // warps 2-3: prefetch next layer's Wqkv + bqkv into the shadow
            const int t = tid - 64;
            for (int i = t; i < 768; i += 64) s_wq[i] = Wqkv[(l + 1) * 768 + i];
            if (t < 48) s_bq[t] = bqkv[(l + 1) * 48 + t];
        }
        __syncthreads();

        // ---- per-token: attn_out + residual + LN1 + FF + residual + LN2 ----
        if (tid < SEQ) {
            float cx[16];
            {
                const float4* c4 = (const float4*)(s_buf + tid * HPAD);
                #pragma unroll
                for (int j = 0; j < 4; j++) {
                    const float4 v = c4[j];
                    cx[4*j] = v.x; cx[4*j+1] = v.y; cx[4*j+2] = v.z; cx[4*j+3] = v.w;
                }
            }
            float res[16];
            {
                const float4* r4 = (const float4*)(s_h + tid * HPAD);
                #pragma unroll
                for (int j = 0; j < 4; j++) {
                    const float4 v = r4[j];
                    res[4*j] = v.x; res[4*j+1] = v.y; res[4*j+2] = v.z; res[4*j+3] = v.w;
                }
            }
            float pre[16];
            float mu = 0.f;
            #pragma unroll
            for (int d = 0; d < 16; d++) {
                const float* wr = s_wo + d * 16;      // broadcast reads
                float acc = s_bo[d];
                #pragma unroll
                for (int e = 0; e < 16; e++) acc = fmaf(cx[e], wr[e], acc);
                acc += res[d];
                pre[d] = acc;
                mu += acc;
            }
            mu *= (1.f / 16.f);
            float var = 0.f;
            #pragma unroll
            for (int d = 0; d < 16; d++) { const float c = pre[d] - mu; var = fmaf(c, c, var); }
            float rs = rsqrtf(var * (1.f / 16.f) + 1e-5f);

            float hloc[16];
            #pragma unroll
            for (int d = 0; d < 16; d++)
                hloc[d] = (pre[d] - mu) * rs * s_g1[d] + s_be1[d];

            float ff1[16];
            #pragma unroll
            for (int f = 0; f < 16; f++) {
                const float* wr = s_w1 + f * 16;
                float acc = s_b1[f];
                #pragma unroll
                for (int d = 0; d < 16; d++) acc = fmaf(hloc[d], wr[d], acc);
                ff1[f] = fmaxf(acc, 0.f);
            }
            mu = 0.f;
            #pragma unroll
            for (int d = 0; d < 16; d++) {
                const float* wr = s_w2 + d * 16;
                float acc = s_b2[d];
                #pragma unroll
                for (int f = 0; f < 16; f++) acc = fmaf(ff1[f], wr[f], acc);
                acc += hloc[d];
                pre[d] = acc;
                mu += acc;
            }
            mu *= (1.f / 16.f);
            var = 0.f;
            #pragma unroll
            for (int d = 0; d < 16; d++) { const float c = pre[d] - mu; var = fmaf(c, c, var); }
            rs = rsqrtf(var * (1.f / 16.f) + 1e-5f);
            {
                float4* o4 = (float4*)(s_h + tid * HPAD);
                #pragma unroll
                for (int j = 0; j < 4; j++) {
                    float4 v;
                    v.x = (pre[4*j]   - mu) * rs * s_g2[4*j]   + s_be2[4*j];
                    v.y = (pre[4*j+1] - mu) * rs * s_g2[4*j+1] + s_be2[4*j+1];
                    v.z = (pre[4*j+2] - mu) * rs * s_g2[4*j+2] + s_be2[4*j+2];
                    v.w = (pre[4*j+3] - mu) * rs * s_g2[4*j+3] + s_be2[4*j+3];
                    o4[j] = v;
                }
            }
        }
        __syncthreads();
    }

    // ---- final LN on cls token (row 0), then 16->100->1 head + sigmoid ----
    if (tid == 0) {
        float r[16];
        float mu = 0.f;
        #pragma unroll
        for (int d = 0; d < 16; d++) { r[d] = s_h[d]; mu += r[d]; }
        mu *= (1.f / 16.f);
        float var = 0.f;
        #pragma unroll
        for (int d = 0; d < 16; d++) { const float c = r[d] - mu; var = fmaf(c, c, var); }
        const float rs = rsqrtf(var * (1.f / 16.f) + 1e-5f);
        #pragma unroll
        for (int d = 0; d < 16; d++) s_buf[d] = (r[d] - mu) * rs * lnfg[d] + lnfb[d];
    }
    __syncthreads();
    if (tid < 100) {
        const float* wr = endw + tid * 16;
        float acc = endb[tid];
        #pragma unroll
        for (int d = 0; d < 16; d++) acc = fmaf(s_buf[d], wr[d], acc);
        s_buf[512 + tid] = acc * headw[tid];   // fold head_w in
    }
    __syncthreads();
    if (tid == 0) {
        float z = headb[0];
        for (int i = 0; i < 100; i++) z += s_buf[512 + i];
        out[b] = 1.f / (1.f + __expf(-z));
    }
}

extern "C" void kernel_launch(void* const* d_in, const int* in_sizes, int n_in,
                              void* d_out, int out_size) {
    const float* x      = (const float*)d_in[0];
    const float* conv_w = (const float*)d_in[1];
    const float* conv_b = (const float*)d_in[2];
    const float* cls    = (const float*)d_in[3];
    const float* Wqkv   = (const float*)d_in[4];
    const float* bqkv   = (const float*)d_in[5];
    const float* Wo     = (const float*)d_in[6];
    const float* bo     = (const float*)d_in[7];
    const float* W1     = (const float*)d_in[8];
    const float* b1     = (const float*)d_in[9];
    const float* W2     = (const float*)d_in[10];
    const float* b2     = (const float*)d_in[11];
    const float* ln1g   = (const float*)d_in[12];
    const float* ln1b   = (const float*)d_in[13];
    const float* ln2g   = (const float*)d_in[14];
    const float* ln2b   = (const float*)d_in[15];
    const float* lnfg   = (const float*)d_in[16];
    const float* lnfb   = (const float*)d_in[17];
    const float* endw   = (const float*)d_in[18];
    const float* endb   = (const float*)d_in[19];
    const float* headw  = (const float*)d_in[20];
    const float* headb  = (const float*)d_in[21];
    float* out = (float*)d_out;

    const int B = in_sizes[0] / 3500;   // 2048
    TorrinE0_kernel<<<B, NTH>>>(x, conv_w, conv_b, cls, Wqkv, bqkv, Wo, bo,
                                W1, b1, W2, b2, ln1g, ln1b, ln2g, ln2b,
                                lnfg, lnfb, endw, endb, headw, headb, out);
}

// round 6
// speedup vs baseline: 1.8401x; 1.8401x over previous
#include <cuda_runtime.h>
#include <cuda_bf16.h>

#define NTH 128
#define SEQ 101
#define HPAD 20   // padded row stride for D=16 activations (bank-conflict-free)

// q pre-scale: (1/sqrt(head_dim=2)) * log2(e), so exp(score) == exp2(q'.k)
#define QSC (0.7071067811865476f * 1.4426950408889634f)

typedef unsigned long long ull;

__device__ __forceinline__ ull pack2(float a, float b) {
    ull r; asm("mov.b64 %0, {%1, %2};" : "=l"(r) : "f"(a), "f"(b)); return r;
}
__device__ __forceinline__ void unpack2(ull p, float& a, float& b) {
    asm("mov.b64 {%0, %1}, %2;" : "=f"(a), "=f"(b) : "l"(p));
}
__device__ __forceinline__ ull fma2u(ull a, ull b, ull c) {
    ull d; asm("fma.rn.f32x2 %0, %1, %2, %3;" : "=l"(d) : "l"(a), "l"(b), "l"(c)); return d;
}
__device__ __forceinline__ ull mul2u(ull a, ull b) {
    ull d; asm("mul.rn.f32x2 %0, %1, %2;" : "=l"(d) : "l"(a), "l"(b)); return d;
}
__device__ __forceinline__ ull add2u(ull a, ull b) {
    ull d; asm("add.rn.f32x2 %0, %1, %2;" : "=l"(d) : "l"(a), "l"(b)); return d;
}
__device__ __forceinline__ float ex2f(float x) {
    float e; asm("ex2.approx.ftz.f32 %0, %1;" : "=f"(e) : "f"(x)); return e;
}

#define XBUF 2048          // x staged in two chunks; also ctx (SEQ*HPAD=2020) later
#define CHUNK0_PATCHES 58  // 58*35 = 2030 <= 2048

__global__ __launch_bounds__(NTH, 5) void TorrinE0_kernel(
    const float* __restrict__ x,
    const float* __restrict__ conv_w,
    const float* __restrict__ conv_b,
    const float* __restrict__ cls_emb,
    const float* __restrict__ Wqkv,
    const float* __restrict__ bqkv,
    const float* __restrict__ Wo,
    const float* __restrict__ bo,
    const float* __restrict__ W1,
    const float* __restrict__ b1,
    const float* __restrict__ W2,
    const float* __restrict__ b2,
    const float* __restrict__ ln1g, const float* __restrict__ ln1b,
    const float* __restrict__ ln2g, const float* __restrict__ ln2b,
    const float* __restrict__ lnfg, const float* __restrict__ lnfb,
    const float* __restrict__ endw, const float* __restrict__ endb,
    const float* __restrict__ headw, const float* __restrict__ headb,
    float* __restrict__ out)
{
    __shared__ float  s_h[SEQ * HPAD];    // hidden state, padded rows
    __shared__ float2 s_q[8 * SEQ];       // [h][s]  pre-scaled q
    __shared__ float4 s_kv[8 * SEQ];      // [h][t]  {k0,k1,v0,v1}
    __shared__ float  s_buf[XBUF];        // x chunks; later ctx[SEQ*HPAD] + head scratch
    __shared__ float  s_wq[768];
    __shared__ float  s_wo[256], s_w1[256], s_w2[256];
    __shared__ float  s_cw[560];
    __shared__ float  s_bq[48];
    __shared__ float  s_bo[16], s_b1[16], s_b2[16];
    __shared__ float  s_g1[16], s_be1[16], s_g2[16], s_be2[16], s_cb[16];

    const int tid = threadIdx.x;
    const int b   = blockIdx.x;

    // ---- stage x chunk 0 (512 float4 = 2048 floats) + conv weights ----
    {
        const float4* xg = (const float4*)(x + (size_t)b * 3500);
        float4* xb = (float4*)s_buf;
        #pragma unroll 2
        for (int i = tid; i < 512; i += NTH) xb[i] = xg[i];
        for (int i = tid; i < 560; i += NTH) s_cw[i] = conv_w[i];
        if (tid < 16) {
            s_h[tid]  = cls_emb[tid];    // cls token = row 0
            s_cb[tid] = conv_b[tid];
        }
    }
    __syncthreads();

    // ---- conv chunk 0: patches 0..57 ----
    for (int idx = tid; idx < CHUNK0_PATCHES * 16; idx += NTH) {
        const int p = idx >> 4, f = idx & 15;
        const float* xp = s_buf + p * 35;
        const float* wf = s_cw + f * 35;
        float acc = s_cb[f];
        #pragma unroll
        for (int k = 0; k < 35; k++) acc = fmaf(xp[k], wf[k], acc);
        s_h[(p + 1) * HPAD + f] = acc;
    }
    __syncthreads();

    // ---- stage x chunk 1: floats 2030..3499 (1470 floats = 735 float2) ----
    {
        const float2* xg = (const float2*)(x + (size_t)b * 3500 + CHUNK0_PATCHES * 35);
        float2* xb = (float2*)s_buf;
        for (int i = tid; i < 735; i += NTH) xb[i] = xg[i];
    }
    __syncthreads();

    // ---- conv chunk 1: patches 58..99 ----
    for (int idx = tid; idx < (100 - CHUNK0_PATCHES) * 16; idx += NTH) {
        const int p = idx >> 4, f = idx & 15;
        const float* xp = s_buf + p * 35;
        const float* wf = s_cw + f * 35;
        float acc = s_cb[f];
        #pragma unroll
        for (int k = 0; k < 35; k++) acc = fmaf(xp[k], wf[k], acc);
        s_h[(p + CHUNK0_PATCHES + 1) * HPAD + f] = acc;
    }
    __syncthreads();

    for (int l = 0; l < 8; l++) {
        // ---- stage layer weights ----
        for (int i = tid; i < 768; i += NTH) s_wq[i] = Wqkv[l * 768 + i];
        for (int i = tid; i < 256; i += NTH) {
            s_wo[i] = Wo[l * 256 + i];
            s_w1[i] = W1[l * 256 + i];
            s_w2[i] = W2[l * 256 + i];
        }
        if (tid < 48) s_bq[tid] = bqkv[l * 48 + tid];
        if (tid < 16) {
            s_bo[tid]  = bo[l * 16 + tid];
            s_b1[tid]  = b1[l * 16 + tid];
            s_b2[tid]  = b2[l * 16 + tid];
            s_g1[tid]  = ln1g[l * 16 + tid];
            s_be1[tid] = ln1b[l * 16 + tid];
            s_g2[tid]  = ln2g[l * 16 + tid];
            s_be2[tid] = ln2b[l * 16 + tid];
        }
        __syncthreads();

        // ---- QKV projection: one thread per token; weight reads broadcast ----
        for (int s = tid; s < SEQ; s += NTH) {
            float hr[16];
            const float4* h4 = (const float4*)(s_h + s * HPAD);
            #pragma unroll
            for (int j = 0; j < 4; j++) {
                const float4 v = h4[j];
                hr[4*j] = v.x; hr[4*j+1] = v.y; hr[4*j+2] = v.z; hr[4*j+3] = v.w;
            }
            #pragma unroll
            for (int h = 0; h < 8; h++) {
                float acc[6];
                #pragma unroll
                for (int r = 0; r < 6; r++) {
                    const int e = (r >> 1) * 16 + 2 * h + (r & 1);
                    const float4* w4 = (const float4*)(s_wq + e * 16);
                    float a = s_bq[e];
                    #pragma unroll
                    for (int j = 0; j < 4; j++) {
                        const float4 wv = w4[j];
                        a = fmaf(hr[4*j],   wv.x, a);
                        a = fmaf(hr[4*j+1], wv.y, a);
                        a = fmaf(hr[4*j+2], wv.z, a);
                        a = fmaf(hr[4*j+3], wv.w, a);
                    }
                    acc[r] = a;
                }
                s_q[h * SEQ + s]  = make_float2(acc[0] * QSC, acc[1] * QSC);
                s_kv[h * SEQ + s] = make_float4(acc[2], acc[3], acc[4], acc[5]);
            }
        }
        __syncthreads();

        // ---- attention: 16 threads/head x 7 queries (3 pairs + 1 single).
        //      All 4 warps issue; one LDS.128 per (h,t) amortized over 7 q. ----
        {
            const int h  = tid >> 4;          // 0..7
            const int j  = tid & 15;          // 0..15
            const int s0 = j * 7;
            const float2* qh = s_q + h * SEQ;

            ull q0p[3], q1p[3];
            #pragma unroll
            for (int p = 0; p < 3; p++) {
                const float2 qa = qh[min(s0 + 2*p,     SEQ - 1)];
                const float2 qb = qh[min(s0 + 2*p + 1, SEQ - 1)];
                q0p[p] = pack2(qa.x, qb.x);
                q1p[p] = pack2(qa.y, qb.y);
            }
            const float2 qs = qh[min(s0 + 6, SEQ - 1)];

            ull sum2[3], c0p[3], c1p[3];
            #pragma unroll
            for (int p = 0; p < 3; p++) {
                sum2[p] = pack2(0.f, 0.f);
                c0p[p]  = pack2(0.f, 0.f);
                c1p[p]  = pack2(0.f, 0.f);
            }
            float sums = 0.f, c0s = 0.f, c1s = 0.f;

            const float4* kp = s_kv + h * SEQ;
            #pragma unroll 2
            for (int t = 0; t < SEQ; t++) {
                const float4 kv = kp[t];
                const ull k0b = pack2(kv.x, kv.x);
                const ull k1b = pack2(kv.y, kv.y);
                const ull v0b = pack2(kv.z, kv.z);
                const ull v1b = pack2(kv.w, kv.w);
                #pragma unroll
                for (int p = 0; p < 3; p++) {
                    const ull sc2 = fma2u(q1p[p], k1b, mul2u(q0p[p], k0b));
                    float sa, sb;
                    unpack2(sc2, sa, sb);
                    const ull e01 = pack2(ex2f(sa), ex2f(sb));
                    sum2[p] = add2u(sum2[p], e01);
                    c0p[p]  = fma2u(e01, v0b, c0p[p]);
                    c1p[p]  = fma2u(e01, v1b, c1p[p]);
                }
                const float sc = fmaf(qs.x, kv.x, qs.y * kv.y);
                const float e  = ex2f(sc);
                sums += e;
                c0s = fmaf(e, kv.z, c0s);
                c1s = fmaf(e, kv.w, c1s);
            }
            #pragma unroll
            for (int p = 0; p < 3; p++) {
                float sa, sb, a0, b0, a1, b1;
                unpack2(sum2[p], sa, sb);
                unpack2(c0p[p],  a0, b0);
                unpack2(c1p[p],  a1, b1);
                const int s_a = min(s0 + 2*p,     SEQ - 1);
                const int s_b = min(s0 + 2*p + 1, SEQ - 1);
                const float ia = __fdividef(1.f, sa);
                const float ib = __fdividef(1.f, sb);
                *(float2*)(s_buf + s_a * HPAD + 2*h) = make_float2(a0 * ia, a1 * ia);
                *(float2*)(s_buf + s_b * HPAD + 2*h) = make_float2(b0 * ib, b1 * ib);
            }
            {
                const int s = min(s0 + 6, SEQ - 1);
                const float inv = __fdividef(1.f, sums);
                *(float2*)(s_buf + s * HPAD + 2*h) = make_float2(c0s * inv, c1s * inv);
            }
        }
        __syncthreads();

        // ---- per-token: attn_out + residual + LN1 + FF + residual + LN2 ----
        if (tid < SEQ) {
            float cx[16];
            {
                const float4* c4 = (const float4*)(s_buf + tid * HPAD);
                #pragma unroll
                for (int j = 0; j < 4; j++) {
                    const float4 v = c4[j];
                    cx[4*j] = v.x; cx[4*j+1] = v.y; cx[4*j+2] = v.z; cx[4*j+3] = v.w;
                }
            }
            float res[16];
            {
                const float4* r4 = (const float4*)(s_h + tid * HPAD);
                #pragma unroll
                for (int j = 0; j < 4; j++) {
                    const float4 v = r4[j];
                    res[4*j] = v.x; res[4*j+1] = v.y; res[4*j+2] = v.z; res[4*j+3] = v.w;
                }
            }
            float pre[16];
            float mu = 0.f;
            #pragma unroll
            for (int d = 0; d < 16; d++) {
                const float* wr = s_wo + d * 16;      // broadcast reads
                float acc = s_bo[d];
                #pragma unroll
                for (int e = 0; e < 16; e++) acc = fmaf(cx[e], wr[e], acc);
                acc += res[d];
                pre[d] = acc;
                mu += acc;
            }
            mu *= (1.f / 16.f);
            float var = 0.f;
            #pragma unroll
            for (int d = 0; d < 16; d++) { const float c = pre[d] - mu; var = fmaf(c, c, var); }
            float rs = rsqrtf(var * (1.f / 16.f) + 1e-5f);

            float hloc[16];
            #pragma unroll
            for (int d = 0; d < 16; d++)
                hloc[d] = (pre[d] - mu) * rs * s_g1[d] + s_be1[d];

            float ff1[16];
            #pragma unroll
            for (int f = 0; f < 16; f++) {
                const float* wr = s_w1 + f * 16;
                float acc = s_b1[f];
                #pragma unroll
                for (int d = 0; d < 16; d++) acc = fmaf(hloc[d], wr[d], acc);
                ff1[f] = fmaxf(acc, 0.f);
            }
            mu = 0.f;
            #pragma unroll
            for (int d = 0; d < 16; d++) {
                const float* wr = s_w2 + d * 16;
                float acc = s_b2[d];
                #pragma unroll
                for (int f = 0; f < 16; f++) acc = fmaf(ff1[f], wr[f], acc);
                acc += hloc[d];
                pre[d] = acc;
                mu += acc;
            }
            mu *= (1.f / 16.f);
            var = 0.f;
            #pragma unroll
            for (int d = 0; d < 16; d++) { const float c = pre[d] - mu; var = fmaf(c, c, var); }
            rs = rsqrtf(var * (1.f / 16.f) + 1e-5f);
            {
                float4* o4 = (float4*)(s_h + tid * HPAD);
                #pragma unroll
                for (int j = 0; j < 4; j++) {
                    float4 v;
                    v.x = (pre[4*j]   - mu) * rs * s_g2[4*j]   + s_be2[4*j];
                    v.y = (pre[4*j+1] - mu) * rs * s_g2[4*j+1] + s_be2[4*j+1];
                    v.z = (pre[4*j+2] - mu) * rs * s_g2[4*j+2] + s_be2[4*j+2];
                    v.w = (pre[4*j+3] - mu) * rs * s_g2[4*j+3] + s_be2[4*j+3];
                    o4[j] = v;
                }
            }
        }
        __syncthreads();
    }

    // ---- final LN on cls token (row 0), then 16->100->1 head + sigmoid ----
    if (tid == 0) {
        float r[16];
        float mu = 0.f;
        #pragma unroll
        for (int d = 0; d < 16; d++) { r[d] = s_h[d]; mu += r[d]; }
        mu *= (1.f / 16.f);
        float var = 0.f;
        #pragma unroll
        for (int d = 0; d < 16; d++) { const float c = r[d] - mu; var = fmaf(c, c, var); }
        const float rs = rsqrtf(var * (1.f / 16.f) + 1e-5f);
        #pragma unroll
        for (int d = 0; d < 16; d++) s_buf[d] = (r[d] - mu) * rs * lnfg[d] + lnfb[d];
    }
    __syncthreads();
    if (tid < 100) {
        const float* wr = endw + tid * 16;
        float acc = endb[tid];
        #pragma unroll
        for (int d = 0; d < 16; d++) acc = fmaf(s_buf[d], wr[d], acc);
        s_buf[1024 + tid] = acc * headw[tid];   // fold head_w in
    }
    __syncthreads();
    if (tid == 0) {
        float z = headb[0];
        for (int i = 0; i < 100; i++) z += s_buf[1024 + i];
        out[b] = 1.f / (1.f + __expf(-z));
    }
}

extern "C" void kernel_launch(void* const* d_in, const int* in_sizes, int n_in,
                              void* d_out, int out_size) {
    const float* x      = (const float*)d_in[0];
    const float* conv_w = (const float*)d_in[1];
    const float* conv_b = (const float*)d_in[2];
    const float* cls    = (const float*)d_in[3];
    const float* Wqkv   = (const float*)d_in[4];
    const float* bqkv   = (const float*)d_in[5];
    const float* Wo     = (const float*)d_in[6];
    const float* bo     = (const float*)d_in[7];
    const float* W1     = (const float*)d_in[8];
    const float* b1     = (const float*)d_in[9];
    const float* W2     = (const float*)d_in[10];
    const float* b2     = (const float*)d_in[11];
    const float* ln1g   = (const float*)d_in[12];
    const float* ln1b   = (const float*)d_in[13];
    const float* ln2g   = (const float*)d_in[14];
    const float* ln2b   = (const float*)d_in[15];
    const float* lnfg   = (const float*)d_in[16];
    const float* lnfb   = (const float*)d_in[17];
    const float* endw   = (const float*)d_in[18];
    const float* endb   = (const float*)d_in[19];
    const float* headw  = (const float*)d_in[20];
    const float* headb  = (const float*)d_in[21];
    float* out = (float*)d_out;

    const int B = in_sizes[0] / 3500;   // 2048
    TorrinE0_kernel<<<B, NTH>>>(x, conv_w, conv_b, cls, Wqkv, bqkv, Wo, bo,
                                W1, b1, W2, b2, ln1g, ln1b, ln2g, ln2b,
                                lnfg, lnfb, endw, endb, headw, headb, out);
}